// round 1
// baseline (speedup 1.0000x reference)
#include <cuda_runtime.h>
#include <cstdint>

// Problem constants (from reference):
//   x:     [B=4, N=64,   D=1024] fp32
//   cache: [B=4, S=8192, D=1024] fp32
//   out:   [B=4, S=8192, D=1024] fp32
// out[b, s, :] = cache[b, s+N, :]        for s <  S-N
// out[b, s, :] = x[b, s-(S-N), :]        for s >= S-N

static constexpr int B = 4;
static constexpr int S = 8192;
static constexpr int D = 1024;
static constexpr int N = 64;
static constexpr int D4 = D / 4;               // 256 float4 per row
static constexpr long long ROW4_PER_B = (long long)S * D4;   // float4 per batch
static constexpr long long TOTAL4 = (long long)B * ROW4_PER_B; // 8,388,608

__global__ __launch_bounds__(256)
void roll_cache_kernel(const float4* __restrict__ x4,
                       const float4* __restrict__ cache4,
                       float4* __restrict__ out4)
{
    long long idx = (long long)blockIdx.x * blockDim.x + threadIdx.x;
    if (idx >= TOTAL4) return;

    // decompose: idx = b * (S*D4) + s * D4 + d
    int b = (int)(idx / ROW4_PER_B);
    int rem = (int)(idx - (long long)b * ROW4_PER_B);
    int s = rem >> 8;          // / 256
    int d = rem & 255;         // % 256

    float4 v;
    if (s < S - N) {
        v = cache4[(long long)b * ROW4_PER_B + (long long)(s + N) * D4 + d];
    } else {
        v = x4[((long long)b * N + (s - (S - N))) * D4 + d];
    }
    out4[idx] = v;
}

extern "C" void kernel_launch(void* const* d_in, const int* in_sizes, int n_in,
                              void* d_out, int out_size)
{
    const float4* x4     = (const float4*)d_in[0];   // x: [B, N, D]
    const float4* cache4 = (const float4*)d_in[1];   // cache: [B, S, D]
    float4* out4 = (float4*)d_out;

    const int threads = 256;
    const long long blocks = (TOTAL4 + threads - 1) / threads;  // 32768
    roll_cache_kernel<<<(unsigned)blocks, threads>>>(x4, cache4, out4);
}